// round 7
// baseline (speedup 1.0000x reference)
#include <cuda_runtime.h>
#include <cstdint>

// Problem constants (fixed shapes for this problem)
#define Bc 8
#define Hc 1024
#define Ec 512
#define Vc 32000
#define Tc 100
#define KVc 1536   // H + E   (x_v width)
#define KKc 2560   // 2H + E  (x_k width)

#define GRID_MAIN 296          // 2 blocks per SM on 148 SMs, single wave
// 8000 tiles = 296*27 + 8 -> first 8 blocks take 28 tiles, rest 27

// Scratch (device globals; no runtime allocation allowed)
__device__ float g_ekval[Bc * Vc];             // e_k values (valid where topic word present)
__device__ float g_psum[GRID_MAIN * Bc];       // per-BLOCK partial softmax sums (ungated)
__device__ float g_rinv[Bc];                   // reciprocal corrected row sums

// ---------------------------------------------------------------------------
// Kernel 1: main GEMV (ungated) + embedded distributed e_k dots.
//  - proven R3/R5 GEMV core: 48 KB static smem, 2 blocks/SM, 4 rows x 8
//    batches per warp-tile, double-buffered W loads, butterfly reduce.
//  - each warp additionally owns at most ONE of the 800 (b,t) topic pairs
//    (spread evenly across all blocks) and computes
//    e_k = x_k . W_K[idx] + b_K[idx] -> g_ekval. Nothing in this kernel
//    consumes g_ekval, so the dots are off the critical path.
//  - epilogue is gate-free: p = exp(tanh(e_v + b_V)).
// ---------------------------------------------------------------------------
__global__ void __launch_bounds__(256, 2) main_kernel(const float* __restrict__ outp,
                                                      const float* __restrict__ inp,
                                                      const float* __restrict__ ctx,
                                                      const int*   __restrict__ topics,
                                                      const float* __restrict__ WV,
                                                      const float* __restrict__ bV,
                                                      const float* __restrict__ WK,
                                                      const float* __restrict__ bK,
                                                      float* __restrict__ out) {
    __shared__ float xs[Bc * KVc];   // 49152 bytes (exactly 48 KB)
    __shared__ float sm_ps[8 * Bc];  // per-warp batch sums

    int tid  = threadIdx.x;
    int warp = tid >> 5;
    int lane = tid & 31;
    int blk  = blockIdx.x;

    // cooperative fill of x_v = concat(output, input_step) per batch
    for (int i = tid; i < (Bc * KVc) / 4; i += 256) {
        int fi = i * 4;
        int b = fi / KVc;
        int c = fi % KVc;
        float4 v;
        if (c < Hc) v = *(const float4*)(outp + b * Hc + c);
        else        v = *(const float4*)(inp  + b * Ec + (c - Hc));
        *(float4*)(xs + fi) = v;
    }
    __syncthreads();

    // ---- embedded e_k dot: warp 0/1 of every block, warp 2 of blocks <208 ----
    // pair p: warp0 -> blk, warp1 -> 296+blk, warp2 -> 592+blk (blk<208)
    {
        int p = -1;
        if (warp < 2)                      p = warp * GRID_MAIN + blk;
        else if (warp == 2 && blk < 208)   p = 2 * GRID_MAIN + blk;
        if (p >= 0) {
            int b   = p / Tc;
            int idx = topics[p];
            if (idx != 0) {
                const float* wrow = WK + (size_t)idx * KKc;
                float s = 0.f;
                #pragma unroll
                for (int i = 0; i < 20; i++) {
                    int c = i * 128 + lane * 4;
                    float4 wv = *(const float4*)(wrow + c);
                    float4 xv;
                    if (c < Hc)            xv = *(const float4*)(outp + b * Hc + c);
                    else if (c < Hc + Ec)  xv = *(const float4*)(inp  + b * Ec + (c - Hc));
                    else                   xv = *(const float4*)(ctx  + b * Hc + (c - Hc - Ec));
                    s += wv.x * xv.x + wv.y * xv.y + wv.z * xv.z + wv.w * xv.w;
                }
                #pragma unroll
                for (int h = 16; h >= 1; h >>= 1) s += __shfl_xor_sync(0xffffffffu, s, h);
                if (lane == 0) g_ekval[b * Vc + idx] = s + __ldg(bK + idx);
            }
        }
    }

    // ---- GEMV over this block's contiguous tile chunk ----
    int b = lane & 7;
    int r = lane >> 3;
    float lsum = 0.f;

    int tbase = blk * 27 + (blk < 8 ? blk : 8);
    int tcnt  = 27 + (blk < 8 ? 1 : 0);

    #pragma unroll 1
    for (int k = warp; k < tcnt; k += 8) {
        int tile = tbase + k;
        int w0 = tile * 4;
        float acc[32];
        #pragma unroll
        for (int j = 0; j < 32; j++) acc[j] = 0.f;

        const float* Wp = WV + (size_t)w0 * KVc + lane * 4;

        // double-buffered W loads
        float4 wc0 = *(const float4*)(Wp);
        float4 wc1 = *(const float4*)(Wp + KVc);
        float4 wc2 = *(const float4*)(Wp + 2 * KVc);
        float4 wc3 = *(const float4*)(Wp + 3 * KVc);

        #pragma unroll 2
        for (int it = 0; it < 12; it++) {
            float4 wn0, wn1, wn2, wn3;
            if (it < 11) {
                const float* Pn = Wp + (it + 1) * 128;
                wn0 = *(const float4*)(Pn);
                wn1 = *(const float4*)(Pn + KVc);
                wn2 = *(const float4*)(Pn + 2 * KVc);
                wn3 = *(const float4*)(Pn + 3 * KVc);
            }
            int xb = it * 128 + lane * 4;
            #pragma unroll
            for (int bb = 0; bb < 8; bb++) {
                float4 xv = *(const float4*)(xs + bb * KVc + xb);
                acc[0 * 8 + bb] = fmaf(wc0.x, xv.x, acc[0 * 8 + bb]);
                acc[0 * 8 + bb] = fmaf(wc0.y, xv.y, acc[0 * 8 + bb]);
                acc[0 * 8 + bb] = fmaf(wc0.z, xv.z, acc[0 * 8 + bb]);
                acc[0 * 8 + bb] = fmaf(wc0.w, xv.w, acc[0 * 8 + bb]);
                acc[1 * 8 + bb] = fmaf(wc1.x, xv.x, acc[1 * 8 + bb]);
                acc[1 * 8 + bb] = fmaf(wc1.y, xv.y, acc[1 * 8 + bb]);
                acc[1 * 8 + bb] = fmaf(wc1.z, xv.z, acc[1 * 8 + bb]);
                acc[1 * 8 + bb] = fmaf(wc1.w, xv.w, acc[1 * 8 + bb]);
                acc[2 * 8 + bb] = fmaf(wc2.x, xv.x, acc[2 * 8 + bb]);
                acc[2 * 8 + bb] = fmaf(wc2.y, xv.y, acc[2 * 8 + bb]);
                acc[2 * 8 + bb] = fmaf(wc2.z, xv.z, acc[2 * 8 + bb]);
                acc[2 * 8 + bb] = fmaf(wc2.w, xv.w, acc[2 * 8 + bb]);
                acc[3 * 8 + bb] = fmaf(wc3.x, xv.x, acc[3 * 8 + bb]);
                acc[3 * 8 + bb] = fmaf(wc3.y, xv.y, acc[3 * 8 + bb]);
                acc[3 * 8 + bb] = fmaf(wc3.z, xv.z, acc[3 * 8 + bb]);
                acc[3 * 8 + bb] = fmaf(wc3.w, xv.w, acc[3 * 8 + bb]);
            }
            wc0 = wn0; wc1 = wn1; wc2 = wn2; wc3 = wn3;
        }

        // butterfly transpose-reduce: 31 shuffles; lane l ends with sum of acc[l]
        #pragma unroll
        for (int h = 16; h >= 1; h >>= 1) {
            #pragma unroll
            for (int j = 0; j < h; j++) {
                float lo = acc[j];
                float hi = acc[j + h];
                float mine = (lane & h) ? hi : lo;
                float send = (lane & h) ? lo : hi;
                float recv = __shfl_xor_sync(0xffffffffu, send, h);
                acc[j] = mine + recv;
            }
        }

        int w = w0 + r;
        float en = tanhf(acc[0] + __ldg(bV + w));
        float p = __expf(en);
        out[b * Vc + w] = p;
        lsum += p;
    }

    // lanes {l, l^8, l^16, l^24} share batch b = l&7 -> combine, lane<8 writes
    lsum += __shfl_xor_sync(0xffffffffu, lsum, 8);
    lsum += __shfl_xor_sync(0xffffffffu, lsum, 16);
    if (lane < 8) sm_ps[warp * 8 + b] = lsum;
    __syncthreads();

    // block-level deterministic combine: 8 warps -> one value per batch
    if (tid < 8) {
        float s = 0.f;
        #pragma unroll
        for (int wv = 0; wv < 8; wv++) s += sm_ps[wv * 8 + tid];
        g_psum[blockIdx.x * 8 + tid] = s;
    }
}

// ---------------------------------------------------------------------------
// Kernel 2: fix-up. One block per batch (grid 8, 256 threads).
//  - smem scan of the batch's 100 topic ids: thread t is responsible for id
//    tw[t] iff it's the FIRST occurrence; cnt = total occurrences.
//  - patches out[b,w] with the gated value p_new = exp(tanh(cnt * e_k)),
//    accumulating delta = p_new - p_old in a fixed deterministic tree.
//  - reduces the 296 per-block psums (fixed order) and writes
//    g_rinv[b] = 1 / (S + delta).
// ---------------------------------------------------------------------------
__global__ void __launch_bounds__(256) fix_kernel(const int* __restrict__ topics,
                                                  float* __restrict__ out) {
    int b   = blockIdx.x;
    int tid = threadIdx.x;
    __shared__ int   tw[Tc];
    __shared__ float sd[128];
    __shared__ float ssum[8];

    if (tid < Tc) tw[tid] = topics[b * Tc + tid];
    if (tid < 128) sd[tid] = 0.f;
    __syncthreads();

    float d = 0.f;
    if (tid < Tc) {
        int w = tw[tid];
        if (w != 0) {
            bool first = true;
            int cnt = 0;
            #pragma unroll 4
            for (int j = 0; j < Tc; j++) {
                if (tw[j] == w) {
                    cnt++;
                    if (j < tid) first = false;
                }
            }
            if (first) {
                float pnew = __expf(tanhf((float)cnt * g_ekval[b * Vc + w]));
                float pold = out[b * Vc + w];
                out[b * Vc + w] = pnew;
                d = pnew - pold;
            }
        }
    }
    if (tid < 128) sd[tid] = d;

    // psum reduce (296 values, fixed order)
    float s = 0.f;
    if (tid < GRID_MAIN)       s += g_psum[tid * 8 + b];
    if (tid + 256 < GRID_MAIN) s += g_psum[(tid + 256) * 8 + b];
    #pragma unroll
    for (int h = 16; h >= 1; h >>= 1) s += __shfl_xor_sync(0xffffffffu, s, h);
    if ((tid & 31) == 0) ssum[tid >> 5] = s;
    __syncthreads();

    if (tid == 0) {
        float S = 0.f;
        #pragma unroll
        for (int w = 0; w < 8; w++) S += ssum[w];
        float D = 0.f;
        #pragma unroll 8
        for (int j = 0; j < 128; j++) D += sd[j];
        g_rinv[b] = 1.0f / (S + D);
    }
}

// ---------------------------------------------------------------------------
// Kernel 3: normalize — pure float4 scale stream (4 MB).
// grid 250 x 256 threads: 64000 float4 = 8*32000 floats exactly.
// ---------------------------------------------------------------------------
__global__ void norm_kernel(float* __restrict__ out) {
    int g = blockIdx.x * 256 + threadIdx.x;   // 0..63999
    int b = g >> 13;                          // 8192 float4 per... (32000/4 = 8000)
    b = g / 8000;
    float r = g_rinv[b];
    float4 v = ((float4*)out)[g];
    v.x *= r; v.y *= r; v.z *= r; v.w *= r;
    ((float4*)out)[g] = v;
}

// ---------------------------------------------------------------------------
// Launch (3 kernels)
// Input order: output, input_step, context, topic_indexs, [topic_length],
//              W_V, b_V, W_K, b_K
// ---------------------------------------------------------------------------
extern "C" void kernel_launch(void* const* d_in, const int* in_sizes, int n_in,
                              void* d_out, int out_size) {
    const float* outp   = (const float*)d_in[0];
    const float* inp    = (const float*)d_in[1];
    const float* ctx    = (const float*)d_in[2];
    const int*   topics = (const int*)d_in[3];

    int base = 4;
    if (n_in >= 9 && in_sizes[4] <= 4) base = 5;   // skip topic_length scalar

    const float* WV = (const float*)d_in[base + 0];
    const float* bV = (const float*)d_in[base + 1];
    const float* WK = (const float*)d_in[base + 2];
    const float* bK = (const float*)d_in[base + 3];
    float* out = (float*)d_out;

    main_kernel<<<GRID_MAIN, 256>>>(outp, inp, ctx, topics, WV, bV, WK, bK, out);
    fix_kernel<<<Bc, 256>>>(topics, out);
    norm_kernel<<<250, 256>>>(out);
}